// round 1
// baseline (speedup 1.0000x reference)
#include <cuda_runtime.h>
#include <cstdint>

#define NBATCH 32
#define NPB (512*512)                 // 262144 pixels per image
#define BPB 32                        // blocks per batch
#define VEC_PER_BLOCK (NPB/4/BPB)     // 2048 float4 per block
#define NB 4096                       // bins per histogram level

// ---- scratch (static device globals; no runtime allocation) ----
__device__ float d_resv[NBATCH * NPB];          // cached residuals (+inf where unmasked)
__device__ int   d_M[NBATCH];
__device__ int   d_h1[NBATCH][NB];              // level-1 counts (key bits [31:19])
__device__ int   d_h2[NBATCH][NB];              // level-2 counts (key bits [18:7])
__device__ float d_s2[NBATCH][NB];              // level-2 sums
__device__ float d_below1[NBATCH];              // exact sum of values below level-1 bin
__device__ int   d_B1[NBATCH];
__device__ int   d_r1[NBATCH];

// ---- zero scratch each launch (graph replays reuse globals) ----
__global__ void k_zero() {
    int idx = blockIdx.x * blockDim.x + threadIdx.x;
    int stride = gridDim.x * blockDim.x;
    for (int i = idx; i < NBATCH * NB; i += stride) {
        ((int*)d_h1)[i] = 0;
        ((int*)d_h2)[i] = 0;
        ((float*)d_s2)[i] = 0.0f;
    }
    if (idx < NBATCH) { d_M[idx] = 0; d_below1[idx] = 0.0f; }
}

// ---- pass 1: residuals + M + level-1 histogram ----
__global__ void __launch_bounds__(256) k_pass1(const float4* __restrict__ p,
                                               const float4* __restrict__ t,
                                               const int4*   __restrict__ m) {
    __shared__ int sh[NB];
    __shared__ int sM;
    for (int i = threadIdx.x; i < NB; i += 256) sh[i] = 0;
    if (threadIdx.x == 0) sM = 0;
    __syncthreads();

    int b   = blockIdx.x / BPB;
    int blk = blockIdx.x % BPB;
    size_t base = (size_t)b * (NPB / 4) + (size_t)blk * VEC_PER_BLOCK;
    float4* resv = (float4*)d_resv;

    int localM = 0;
    for (int i = threadIdx.x; i < VEC_PER_BLOCK; i += 256) {
        float4 pv = p[base + i];
        float4 tv = t[base + i];
        int4   mv = m[base + i];
        float r0 = fabsf(pv.x - tv.x); int v0 = mv.x > 0;
        float r1 = fabsf(pv.y - tv.y); int v1 = mv.y > 0;
        float r2 = fabsf(pv.z - tv.z); int v2 = mv.z > 0;
        float r3 = fabsf(pv.w - tv.w); int v3 = mv.w > 0;
        const float INF = __int_as_float(0x7F800000);
        float4 o;
        o.x = v0 ? r0 : INF;
        o.y = v1 ? r1 : INF;
        o.z = v2 ? r2 : INF;
        o.w = v3 ? r3 : INF;
        resv[base + i] = o;

        float rr[4] = {r0, r1, r2, r3};
        int   vv[4] = {v0, v1, v2, v3};
        #pragma unroll
        for (int j = 0; j < 4; j++) {
            localM += vv[j];
            unsigned bin = vv[j] ? (__float_as_uint(rr[j]) >> 19) : 0xFFFFFFFFu;
            // aggregate equal bins within the warp: one atomic per distinct bin
            unsigned mask = __match_any_sync(0xFFFFFFFFu, bin);
            int leader = __ffs(mask) - 1;
            if (((int)(threadIdx.x & 31) == leader) && (bin != 0xFFFFFFFFu))
                atomicAdd(&sh[bin], __popc(mask));
        }
    }
    #pragma unroll
    for (int off = 16; off; off >>= 1)
        localM += __shfl_down_sync(0xFFFFFFFFu, localM, off);
    if ((threadIdx.x & 31) == 0) atomicAdd(&sM, localM);
    __syncthreads();

    for (int i = threadIdx.x; i < NB; i += 256) {
        int c = sh[i];
        if (c) atomicAdd(&d_h1[b][i], c);
    }
    if (threadIdx.x == 0) atomicAdd(&d_M[b], sM);
}

// ---- select level-1 bin: warp per batch, warp-scan over 4096 bins ----
__global__ void __launch_bounds__(1024) k_select1() {
    int w = threadIdx.x >> 5;      // batch
    int lane = threadIdx.x & 31;
    int M = d_M[w];
    int k = (int)floorf((float)M * (1.0f - 0.2f));
    int B1 = -1, r1 = 0;
    if (k > 0) {
        int cum = 0;
        for (int base = 0; base < NB; base += 32) {
            int c = d_h1[w][base + lane];
            int s = c;
            #pragma unroll
            for (int off = 1; off < 32; off <<= 1) {
                int n = __shfl_up_sync(0xFFFFFFFFu, s, off);
                if (lane >= off) s += n;
            }
            int total = __shfl_sync(0xFFFFFFFFu, s, 31);
            if (cum + total >= k) {
                unsigned bal = __ballot_sync(0xFFFFFFFFu, cum + s >= k);
                int l = __ffs(bal) - 1;
                int excl = __shfl_sync(0xFFFFFFFFu, s - c, l);
                B1 = base + l;
                r1 = k - (cum + excl);
                break;
            }
            cum += total;
        }
    }
    if (lane == 0) { d_B1[w] = B1; d_r1[w] = r1; }
}

// ---- pass 2: exact sum below B1 + level-2 histogram of the tie bin ----
__global__ void __launch_bounds__(256) k_pass2() {
    __shared__ int   shc[NB];
    __shared__ float shs[NB];
    for (int i = threadIdx.x; i < NB; i += 256) { shc[i] = 0; shs[i] = 0.0f; }
    __syncthreads();

    int b   = blockIdx.x / BPB;
    int blk = blockIdx.x % BPB;
    int B1  = d_B1[b];
    size_t base = (size_t)b * (NPB / 4) + (size_t)blk * VEC_PER_BLOCK;
    const float4* resv = (const float4*)d_resv;

    float localSum = 0.0f;
    if (B1 >= 0) {
        for (int i = threadIdx.x; i < VEC_PER_BLOCK; i += 256) {
            float4 v = resv[base + i];
            float vals[4] = {v.x, v.y, v.z, v.w};
            #pragma unroll
            for (int j = 0; j < 4; j++) {
                unsigned key = __float_as_uint(vals[j]);
                int pre = (int)(key >> 19);
                if (pre < B1) {
                    localSum += vals[j];
                } else if (pre == B1) {
                    int bin = (int)((key >> 7) & 0xFFFu);
                    atomicAdd(&shc[bin], 1);
                    atomicAdd(&shs[bin], vals[j]);
                }
            }
        }
    }
    #pragma unroll
    for (int off = 16; off; off >>= 1)
        localSum += __shfl_down_sync(0xFFFFFFFFu, localSum, off);
    if ((threadIdx.x & 31) == 0) atomicAdd(&d_below1[b], localSum);
    __syncthreads();

    for (int i = threadIdx.x; i < NB; i += 256) {
        int c = shc[i];
        if (c) { atomicAdd(&d_h2[b][i], c); atomicAdd(&d_s2[b][i], shs[i]); }
    }
}

// ---- final: warp per batch scans level-2, then global reduce + normalize ----
__global__ void __launch_bounds__(1024) k_final(float* __restrict__ out) {
    __shared__ float s_loss[32], s_div[32];
    int w = threadIdx.x >> 5;
    int lane = threadIdx.x & 31;
    int M = d_M[w];
    float div = (float)M * (1.0f - 0.2f);
    int k = (int)floorf(div);
    float loss = 0.0f;
    if (k > 0) {
        int B1 = d_B1[w], r1 = d_r1[w];
        int cum = 0; float sum = 0.0f;
        for (int base = 0; base < NB; base += 32) {
            int c  = d_h2[w][base + lane];
            float sv = d_s2[w][base + lane];
            int s = c;
            #pragma unroll
            for (int off = 1; off < 32; off <<= 1) {
                int n = __shfl_up_sync(0xFFFFFFFFu, s, off);
                if (lane >= off) s += n;
            }
            int total = __shfl_sync(0xFFFFFFFFu, s, 31);
            if (cum + total >= r1) {
                unsigned bal = __ballot_sync(0xFFFFFFFFu, cum + s >= r1);
                int l = __ffs(bal) - 1;
                int excl = __shfl_sync(0xFFFFFFFFu, s - c, l);
                int r2 = r1 - (cum + excl);
                float pv = (lane < l) ? sv : 0.0f;
                #pragma unroll
                for (int off = 16; off; off >>= 1)
                    pv += __shfl_xor_sync(0xFFFFFFFFu, pv, off);
                // lower edge of the unresolved bin: rel error <= 2^-16 on tie bin only
                float edge = __uint_as_float(((unsigned)B1 << 19) | ((unsigned)(base + l) << 7));
                loss = d_below1[w] + sum + pv + (float)r2 * edge;
                break;
            }
            cum += total;
            float cs = sv;
            #pragma unroll
            for (int off = 16; off; off >>= 1)
                cs += __shfl_xor_sync(0xFFFFFFFFu, cs, off);
            sum += cs;
        }
    }
    if (lane == 0) { s_loss[w] = loss; s_div[w] = div; }
    __syncthreads();
    if (threadIdx.x < 32) {
        float L = s_loss[threadIdx.x], D = s_div[threadIdx.x];
        #pragma unroll
        for (int off = 16; off; off >>= 1) {
            L += __shfl_xor_sync(0xFFFFFFFFu, L, off);
            D += __shfl_xor_sync(0xFFFFFFFFu, D, off);
        }
        if (threadIdx.x == 0)
            out[0] = (D == 0.0f) ? 0.0f : L / fmaxf(D, 1e-30f);
    }
}

extern "C" void kernel_launch(void* const* d_in, const int* in_sizes, int n_in,
                              void* d_out, int out_size) {
    const float4* p = (const float4*)d_in[0];   // prediction f32 [32,512,512]
    const float4* t = (const float4*)d_in[1];   // target     f32 [32,512,512]
    const int4*   m = (const int4*)d_in[2];     // mask       i32 [32,512,512]
    float* out = (float*)d_out;

    k_zero<<<256, 256>>>();
    k_pass1<<<NBATCH * BPB, 256>>>(p, t, m);
    k_select1<<<1, 1024>>>();
    k_pass2<<<NBATCH * BPB, 256>>>();
    k_final<<<1, 1024>>>(out);
}

// round 4
// speedup vs baseline: 2.1188x; 2.1188x over previous
#include <cuda_runtime.h>
#include <cstdint>

#define NBATCH 32
#define NPB (512*512)                 // 262144 pixels per image
#define BPB 32                        // blocks per batch
#define VEC_PER_BLOCK (NPB/4/BPB)     // 2048 float4 per block
#define NB 4096                       // bins: float bits >> 19 (exp8 + mant4)
#define CNT_SHIFT 44
#define SUM_MASK ((1ull << CNT_SHIFT) - 1ull)
#define FIX_SCALE 262144.0f           // 2^18 fixed-point scale for value sums
#define INV_FIX   (1.0f / 262144.0f)

// packed per-batch histogram: high 20 bits count, low 44 bits fixed-point sum
__device__ unsigned long long d_hist[NBATCH][NB];

// ---- zero scratch each replay ----
__global__ void k_zero() {
    int idx = blockIdx.x * blockDim.x + threadIdx.x;
    int stride = gridDim.x * blockDim.x;
    unsigned long long* h = &d_hist[0][0];
    for (int i = idx; i < NBATCH * NB; i += stride) h[i] = 0ull;
}

// ---- single data pass: packed count+sum histogram ----
__global__ void __launch_bounds__(256) k_pass1(const float4* __restrict__ p,
                                               const float4* __restrict__ t,
                                               const int4*   __restrict__ m) {
    __shared__ unsigned long long sh[NB];
    for (int i = threadIdx.x; i < NB; i += 256) sh[i] = 0ull;
    __syncthreads();

    int b   = blockIdx.x / BPB;
    int blk = blockIdx.x % BPB;
    size_t base = (size_t)b * (NPB / 4) + (size_t)blk * VEC_PER_BLOCK;

    for (int i = threadIdx.x; i < VEC_PER_BLOCK; i += 256) {
        float4 pv = p[base + i];
        float4 tv = t[base + i];
        int4   mv = m[base + i];
        float r[4] = { fabsf(pv.x - tv.x), fabsf(pv.y - tv.y),
                       fabsf(pv.z - tv.z), fabsf(pv.w - tv.w) };
        int   v[4] = { mv.x > 0, mv.y > 0, mv.z > 0, mv.w > 0 };
        #pragma unroll
        for (int j = 0; j < 4; j++) {
            if (v[j]) {
                unsigned bin = __float_as_uint(r[j]) >> 19;       // < 4096 for finite
                unsigned long long q = (unsigned long long)__float2uint_rn(r[j] * FIX_SCALE);
                atomicAdd(&sh[bin], (1ull << CNT_SHIFT) + q);
            }
        }
    }
    __syncthreads();

    for (int i = threadIdx.x; i < NB; i += 256) {
        unsigned long long v = sh[i];
        if (v) atomicAdd(&d_hist[b][i], v);
    }
}

// ---- final: warp per batch, scan histogram, interpolate tie bin ----
__global__ void __launch_bounds__(1024) k_final(float* __restrict__ out) {
    __shared__ float s_loss[32], s_div[32];
    int w    = threadIdx.x >> 5;   // batch
    int lane = threadIdx.x & 31;

    // pass A: total count -> M
    int Mlane = 0;
    for (int base = 0; base < NB; base += 32)
        Mlane += (int)(d_hist[w][base + lane] >> CNT_SHIFT);
    #pragma unroll
    for (int off = 16; off; off >>= 1)
        Mlane += __shfl_xor_sync(0xFFFFFFFFu, Mlane, off);
    int M = Mlane;

    float div = (float)M * (1.0f - 0.2f);
    int k = (int)floorf(div);

    float loss = 0.0f;
    if (k > 0) {
        int cum = 0; float sum = 0.0f;
        for (int base = 0; base < NB; base += 32) {
            unsigned long long v = d_hist[w][base + lane];
            int   c = (int)(v >> CNT_SHIFT);
            float s = (float)(v & SUM_MASK) * INV_FIX;
            // inclusive scan of counts
            int cs = c;
            #pragma unroll
            for (int off = 1; off < 32; off <<= 1) {
                int n = __shfl_up_sync(0xFFFFFFFFu, cs, off);
                if (lane >= off) cs += n;
            }
            int total = __shfl_sync(0xFFFFFFFFu, cs, 31);
            if (cum + total >= k) {
                unsigned bal = __ballot_sync(0xFFFFFFFFu, cum + cs >= k);
                int l = __ffs(bal) - 1;
                int excl = __shfl_sync(0xFFFFFFFFu, cs - c, l);
                int r2 = k - (cum + excl);                    // 1..c[l]
                // sum of bins strictly below l in this chunk
                float pv = (lane < l) ? s : 0.0f;
                #pragma unroll
                for (int off = 16; off; off >>= 1)
                    pv += __shfl_xor_sync(0xFFFFFFFFu, pv, off);
                int   cl = __shfl_sync(0xFFFFFFFFu, c, l);
                float sl = __shfl_sync(0xFFFFFFFFu, s, l);
                float lo = __uint_as_float((unsigned)(base + l) << 19);
                float mbar = sl / (float)cl;
                // matched-mean uniform model: partial = r2*lo + (mbar-lo)*r2^2/c
                float partial = (float)r2 * lo
                              + (mbar - lo) * ((float)r2 * (float)r2) / (float)cl;
                loss = sum + pv + partial;
                break;
            }
            cum += total;
            float cssum = s;
            #pragma unroll
            for (int off = 16; off; off >>= 1)
                cssum += __shfl_xor_sync(0xFFFFFFFFu, cssum, off);
            sum += cssum;
        }
    }

    if (lane == 0) { s_loss[w] = loss; s_div[w] = div; }
    __syncthreads();
    if (threadIdx.x < 32) {
        float L = s_loss[threadIdx.x], D = s_div[threadIdx.x];
        #pragma unroll
        for (int off = 16; off; off >>= 1) {
            L += __shfl_xor_sync(0xFFFFFFFFu, L, off);
            D += __shfl_xor_sync(0xFFFFFFFFu, D, off);
        }
        if (threadIdx.x == 0)
            out[0] = (D == 0.0f) ? 0.0f : L / fmaxf(D, 1e-30f);
    }
}

extern "C" void kernel_launch(void* const* d_in, const int* in_sizes, int n_in,
                              void* d_out, int out_size) {
    const float4* p = (const float4*)d_in[0];   // prediction f32 [32,512,512]
    const float4* t = (const float4*)d_in[1];   // target     f32 [32,512,512]
    const int4*   m = (const int4*)d_in[2];     // mask       i32 [32,512,512]
    float* out = (float*)d_out;

    k_zero<<<128, 256>>>();
    k_pass1<<<NBATCH * BPB, 256>>>(p, t, m);
    k_final<<<1, 1024>>>(out);
}

// round 5
// speedup vs baseline: 2.3152x; 1.0927x over previous
#include <cuda_runtime.h>
#include <cstdint>

#define NBATCH 32
#define NPB (512*512)                 // 262144 pixels per image
#define BPB 32                        // blocks per batch in pass1
#define VEC_PER_BLOCK (NPB/4/BPB)     // 2048 float4 per block
#define NB 4096                       // bins: |residual| bits >> 19 (exp8 + mant4)
#define CNT_SHIFT 44
#define SUM_MASK ((1ull << CNT_SHIFT) - 1ull)

// packed per-batch histogram: bits[63:44] count, bits[43:0] sum of low-19 mantissa bits
__device__ unsigned long long d_hist[NBATCH][NB];
__device__ float d_loss[NBATCH];
__device__ float d_div[NBATCH];

// ---- reconstruct exact per-bin float sum: s = cnt*lo + slow*2^(E-150) ----
__device__ __forceinline__ float bin_sum(int bin, int cnt, unsigned long long slow) {
    if (cnt == 0) return 0.0f;
    float lo = __uint_as_float((unsigned)bin << 19);
    int E = bin >> 4;
    // normals: low19 ulp weight = 2^(E-150); subnormals (E==0): 2^-149
    float w = ldexpf(1.0f, (E == 0) ? -149 : (E - 150));
    return (float)cnt * lo + (float)slow * w;
}

// ---- single data pass: packed count+mantissa-sum histogram ----
__global__ void __launch_bounds__(256) k_pass1(const float4* __restrict__ p,
                                               const float4* __restrict__ t,
                                               const int4*   __restrict__ m) {
    __shared__ unsigned long long sh[NB];
    for (int i = threadIdx.x; i < NB; i += 256) sh[i] = 0ull;
    __syncthreads();

    int b   = blockIdx.x / BPB;
    int blk = blockIdx.x % BPB;
    size_t base = (size_t)b * (NPB / 4) + (size_t)blk * VEC_PER_BLOCK;

    #pragma unroll 2
    for (int i = threadIdx.x; i < VEC_PER_BLOCK; i += 256) {
        float4 pv = p[base + i];
        float4 tv = t[base + i];
        int4   mv = m[base + i];
        float d0 = pv.x - tv.x, d1 = pv.y - tv.y;
        float d2 = pv.z - tv.z, d3 = pv.w - tv.w;
        unsigned bb[4] = {
            __float_as_uint(d0) & 0x7FFFFFFFu,
            __float_as_uint(d1) & 0x7FFFFFFFu,
            __float_as_uint(d2) & 0x7FFFFFFFu,
            __float_as_uint(d3) & 0x7FFFFFFFu };
        int vv[4] = { mv.x > 0, mv.y > 0, mv.z > 0, mv.w > 0 };
        #pragma unroll
        for (int j = 0; j < 4; j++) {
            if (vv[j]) {
                // value = lo(bin) + (bits & 0x7FFFF) * 2^(E-150): pack count + low19
                atomicAdd(&sh[bb[j] >> 19],
                          (1ull << CNT_SHIFT) | (unsigned long long)(bb[j] & 0x7FFFFu));
            }
        }
    }
    __syncthreads();

    for (int i = threadIdx.x; i < NB; i += 256) {
        unsigned long long v = sh[i];
        if (v) atomicAdd(&d_hist[b][i], v);
    }
}

// ---- per-batch finalize: one block per batch; warp0 scans, warps 1-7 zero hist ----
__global__ void __launch_bounds__(256) k_final() {
    __shared__ unsigned long long sh[NB];
    __shared__ int sM;
    int b = blockIdx.x;
    int tid = threadIdx.x;

    if (tid == 0) sM = 0;
    __syncthreads();

    // copy histogram to smem + accumulate M
    int localM = 0;
    for (int i = tid; i < NB; i += 256) {
        unsigned long long v = d_hist[b][i];
        sh[i] = v;
        localM += (int)(v >> CNT_SHIFT);
    }
    #pragma unroll
    for (int off = 16; off; off >>= 1)
        localM += __shfl_down_sync(0xFFFFFFFFu, localM, off);
    if ((tid & 31) == 0) atomicAdd(&sM, localM);
    __syncthreads();

    if (tid >= 32) {
        // warps 1-7: zero this batch's global histogram for the next graph replay
        for (int i = tid - 32; i < NB; i += 224) d_hist[b][i] = 0ull;
    } else {
        // warp 0: find k-th smallest bin and accumulate kept sum from smem
        int lane = tid;
        int M = sM;
        float div = (float)M * (1.0f - 0.2f);
        int k = (int)floorf(div);
        float loss = 0.0f;
        if (k > 0) {
            int cum = 0; float sum = 0.0f;
            for (int base = 0; base < NB; base += 32) {
                unsigned long long v = sh[base + lane];
                int c = (int)(v >> CNT_SHIFT);
                float s = bin_sum(base + lane, c, v & SUM_MASK);
                int cs = c;
                #pragma unroll
                for (int off = 1; off < 32; off <<= 1) {
                    int n = __shfl_up_sync(0xFFFFFFFFu, cs, off);
                    if (lane >= off) cs += n;
                }
                int total = __shfl_sync(0xFFFFFFFFu, cs, 31);
                if (cum + total >= k) {
                    unsigned bal = __ballot_sync(0xFFFFFFFFu, cum + cs >= k);
                    int l = __ffs(bal) - 1;
                    int excl = __shfl_sync(0xFFFFFFFFu, cs - c, l);
                    int r2 = k - (cum + excl);                    // kept count in tie bin
                    float pv = (lane < l) ? s : 0.0f;
                    #pragma unroll
                    for (int off = 16; off; off >>= 1)
                        pv += __shfl_xor_sync(0xFFFFFFFFu, pv, off);
                    int   cl = __shfl_sync(0xFFFFFFFFu, c, l);
                    float sl = __shfl_sync(0xFFFFFFFFu, s, l);
                    float lo = __uint_as_float((unsigned)(base + l) << 19);
                    float mbar = sl / (float)cl;
                    // matched-mean uniform model within tie bin
                    float partial = (float)r2 * lo
                                  + (mbar - lo) * ((float)r2 * (float)r2) / (float)cl;
                    loss = sum + pv + partial;
                    break;
                }
                cum += total;
                float cssum = s;
                #pragma unroll
                for (int off = 16; off; off >>= 1)
                    cssum += __shfl_xor_sync(0xFFFFFFFFu, cssum, off);
                sum += cssum;
            }
        }
        if (lane == 0) { d_loss[b] = loss; d_div[b] = div; }
    }
}

// ---- final reduce: 1 warp ----
__global__ void k_reduce(float* __restrict__ out) {
    int lane = threadIdx.x;
    float L = d_loss[lane];
    float D = d_div[lane];
    #pragma unroll
    for (int off = 16; off; off >>= 1) {
        L += __shfl_xor_sync(0xFFFFFFFFu, L, off);
        D += __shfl_xor_sync(0xFFFFFFFFu, D, off);
    }
    if (lane == 0)
        out[0] = (D == 0.0f) ? 0.0f : L / fmaxf(D, 1e-30f);
}

extern "C" void kernel_launch(void* const* d_in, const int* in_sizes, int n_in,
                              void* d_out, int out_size) {
    const float4* p = (const float4*)d_in[0];   // prediction f32 [32,512,512]
    const float4* t = (const float4*)d_in[1];   // target     f32 [32,512,512]
    const int4*   m = (const int4*)d_in[2];     // mask       i32 [32,512,512]
    float* out = (float*)d_out;

    k_pass1<<<NBATCH * BPB, 256>>>(p, t, m);
    k_final<<<NBATCH, 256>>>();
    k_reduce<<<1, 32>>>(out);
}

// round 6
// speedup vs baseline: 3.0948x; 1.3368x over previous
#include <cuda_runtime.h>
#include <cstdint>

#define NBATCH 32
#define NPB (512*512)                 // 262144 pixels per image
#define VPB_BATCH (NPB/4)             // 65536 float4 per batch
#define BPB 64                        // blocks per batch in pass B
#define VPB (VPB_BATCH/BPB)           // 1024 float4 per block
#define NB 4096                       // bins: |residual| bits >> 19
#define BAND_MAX 1024                 // max band width (bins)
#define CNT_SHIFT 44
#define SUM_MASK ((1ull << CNT_SHIFT) - 1ull)
#define SAMPLE_STRIDE 64              // sample every 64th float4

__device__ unsigned long long d_hist[NBATCH][NB];   // band bins only are touched
__device__ int   d_binlo[NBATCH], d_binhi[NBATCH];
__device__ float d_sumbelow[NBATCH];
__device__ int   d_cntbelow[NBATCH];
__device__ int   d_M[NBATCH];
__device__ float d_loss[NBATCH], d_div[NBATCH];

// exact per-bin float sum: s = cnt*lo(bin) + slow * 2^(E-150)
__device__ __forceinline__ float bin_sum(int bin, int cnt, unsigned long long slow) {
    if (cnt == 0) return 0.0f;
    float lo = __uint_as_float((unsigned)bin << 19);
    int E = bin >> 4;
    float w = ldexpf(1.0f, (E == 0) ? -149 : (E - 150));
    return (float)cnt * lo + (float)slow * w;
}

// ---- pass A: 1/64 sample -> per-batch quantile bracket [BIN_LO, BIN_HI] ----
__global__ void __launch_bounds__(256) k_sample(const float4* __restrict__ p,
                                                const float4* __restrict__ t,
                                                const int4*   __restrict__ m) {
    __shared__ int sh[NB];
    __shared__ int s_nv;
    int b = blockIdx.x, tid = threadIdx.x, lane = tid & 31;
    for (int i = tid; i < NB; i += 256) sh[i] = 0;
    if (tid == 0) { s_nv = 0; d_sumbelow[b] = 0.0f; d_cntbelow[b] = 0; d_M[b] = 0; }
    __syncthreads();

    size_t base = (size_t)b * VPB_BATCH;
    int nv = 0;
    #pragma unroll
    for (int it = 0; it < (VPB_BATCH / SAMPLE_STRIDE) / 256; it++) {
        int i = tid + it * 256;
        size_t idx = base + (size_t)i * SAMPLE_STRIDE;
        float4 pv = p[idx]; float4 tv = t[idx]; int4 mv = m[idx];
        float dd[4] = { pv.x - tv.x, pv.y - tv.y, pv.z - tv.z, pv.w - tv.w };
        int   vv[4] = { mv.x > 0, mv.y > 0, mv.z > 0, mv.w > 0 };
        #pragma unroll
        for (int j = 0; j < 4; j++) {
            if (vv[j]) {
                unsigned bits = __float_as_uint(dd[j]) & 0x7FFFFFFFu;
                atomicAdd(&sh[bits >> 19], 1);
                nv++;
            }
        }
    }
    #pragma unroll
    for (int off = 16; off; off >>= 1) nv += __shfl_down_sync(0xFFFFFFFFu, nv, off);
    if (lane == 0) atomicAdd(&s_nv, nv);
    __syncthreads();

    if (tid < 32) {
        int n = s_nv;
        int binlo = 0, binhi = NB - 1;
        if (n > 16) {
            int ks = (int)((float)n * 0.8f);
            int delta = (int)(10.0f * sqrtf(0.16f * (float)n)) + 24;
            int rlo = ks - delta; if (rlo < 1) rlo = 1;
            int rhi = ks + delta;
            int blo = -1, bhi = -1, cum = 0;
            for (int bs = 0; bs < NB; bs += 32) {
                int c = sh[bs + lane];
                int cs = c;
                #pragma unroll
                for (int off = 1; off < 32; off <<= 1) {
                    int x = __shfl_up_sync(0xFFFFFFFFu, cs, off);
                    if (lane >= off) cs += x;
                }
                int total = __shfl_sync(0xFFFFFFFFu, cs, 31);
                if (blo < 0 && cum + total >= rlo) {
                    unsigned bal = __ballot_sync(0xFFFFFFFFu, cum + cs >= rlo);
                    blo = bs + (__ffs(bal) - 1);
                }
                if (bhi < 0 && cum + total >= rhi) {
                    unsigned bal = __ballot_sync(0xFFFFFFFFu, cum + cs >= rhi);
                    bhi = bs + (__ffs(bal) - 1);
                }
                cum += total;
                if (blo >= 0 && bhi >= 0) break;
            }
            if (blo < 0) blo = NB - 1;
            if (bhi < 0) bhi = NB - 1;
            binlo = blo - 2; if (binlo < 0) binlo = 0;
            binhi = bhi + 2; if (binhi > NB - 1) binhi = NB - 1;
        }
        if (binhi > binlo + BAND_MAX - 1) binhi = binlo + BAND_MAX - 1;
        if (lane == 0) { d_binlo[b] = binlo; d_binhi[b] = binhi; }
    }
}

// ---- pass B: full read; below-band in registers, band via shared atomics ----
__global__ void __launch_bounds__(256) k_passB(const float4* __restrict__ p,
                                               const float4* __restrict__ t,
                                               const int4*   __restrict__ m) {
    __shared__ unsigned long long sh[BAND_MAX];
    __shared__ float s_wsum[8];
    __shared__ int   s_wcnt[8], s_wM[8];
    int tid = threadIdx.x, lane = tid & 31, wid = tid >> 5;
    int b   = blockIdx.x / BPB;
    int blk = blockIdx.x % BPB;
    int BLO = d_binlo[b], BHI = d_binhi[b];

    for (int i = tid; i < BAND_MAX; i += 256) sh[i] = 0ull;
    __syncthreads();

    size_t base = (size_t)b * VPB_BATCH + (size_t)blk * VPB;
    float s0 = 0.f, s1 = 0.f, s2 = 0.f, s3 = 0.f;
    int cnt = 0, Ml = 0;

    #pragma unroll
    for (int it = 0; it < VPB / 256; it++) {
        int i = tid + it * 256;
        float4 pv = p[base + i];
        float4 tv = t[base + i];
        int4   mv = m[base + i];
        unsigned bb[4] = {
            __float_as_uint(pv.x - tv.x) & 0x7FFFFFFFu,
            __float_as_uint(pv.y - tv.y) & 0x7FFFFFFFu,
            __float_as_uint(pv.z - tv.z) & 0x7FFFFFFFu,
            __float_as_uint(pv.w - tv.w) & 0x7FFFFFFFu };
        int vv[4] = { mv.x > 0, mv.y > 0, mv.z > 0, mv.w > 0 };
        float* acc[4] = { &s0, &s1, &s2, &s3 };
        #pragma unroll
        for (int j = 0; j < 4; j++) {
            if (vv[j]) {
                Ml++;
                int bin = (int)(bb[j] >> 19);
                if (bin < BLO) {
                    *acc[j] += __uint_as_float(bb[j]);
                    cnt++;
                } else if (bin <= BHI) {
                    atomicAdd(&sh[bin - BLO],
                              (1ull << CNT_SHIFT) | (unsigned long long)(bb[j] & 0x7FFFFu));
                }
            }
        }
    }

    float s = (s0 + s1) + (s2 + s3);
    #pragma unroll
    for (int off = 16; off; off >>= 1) {
        s   += __shfl_down_sync(0xFFFFFFFFu, s, off);
        cnt += __shfl_down_sync(0xFFFFFFFFu, cnt, off);
        Ml  += __shfl_down_sync(0xFFFFFFFFu, Ml, off);
    }
    if (lane == 0) { s_wsum[wid] = s; s_wcnt[wid] = cnt; s_wM[wid] = Ml; }
    __syncthreads();
    if (tid == 0) {
        float ts = 0.f; int tc = 0, tm = 0;
        #pragma unroll
        for (int w = 0; w < 8; w++) { ts += s_wsum[w]; tc += s_wcnt[w]; tm += s_wM[w]; }
        atomicAdd(&d_sumbelow[b], ts);
        atomicAdd(&d_cntbelow[b], tc);
        atomicAdd(&d_M[b], tm);
    }

    int nband = BHI - BLO + 1;
    for (int i = tid; i < nband; i += 256) {
        unsigned long long v = sh[i];
        if (v) atomicAdd(&d_hist[b][BLO + i], v);
    }
}

// ---- finalize: one block per batch; warp0 scans band, warps 1-7 re-zero it ----
__global__ void __launch_bounds__(256) k_final() {
    __shared__ unsigned long long shb[BAND_MAX];
    int b = blockIdx.x, tid = threadIdx.x, lane = tid & 31;
    int BLO = d_binlo[b], BHI = d_binhi[b];
    int nband = BHI - BLO + 1;

    for (int i = tid; i < nband; i += 256) shb[i] = d_hist[b][BLO + i];
    __syncthreads();

    if (tid >= 32) {
        for (int i = tid - 32; i < nband; i += 224) d_hist[b][BLO + i] = 0ull;
    } else {
        int M = d_M[b];
        float div = (float)M * (1.0f - 0.2f);
        int k = (int)floorf(div);
        float loss = 0.0f;
        if (k > 0) {
            float below = d_sumbelow[b];
            int r1 = k - d_cntbelow[b];
            if (r1 <= 0) {
                loss = below;                       // defensive (bracket miss low)
            } else {
                int cum = 0; float acc = 0.0f; int done = 0;
                for (int j0 = 0; j0 < nband; j0 += 32) {
                    int j = j0 + lane;
                    unsigned long long v = (j < nband) ? shb[j] : 0ull;
                    int c = (int)(v >> CNT_SHIFT);
                    float s = bin_sum(BLO + j, c, v & SUM_MASK);
                    int cs = c;
                    #pragma unroll
                    for (int off = 1; off < 32; off <<= 1) {
                        int x = __shfl_up_sync(0xFFFFFFFFu, cs, off);
                        if (lane >= off) cs += x;
                    }
                    int total = __shfl_sync(0xFFFFFFFFu, cs, 31);
                    if (cum + total >= r1) {
                        unsigned bal = __ballot_sync(0xFFFFFFFFu, cum + cs >= r1);
                        int l = __ffs(bal) - 1;
                        int excl = __shfl_sync(0xFFFFFFFFu, cs - c, l);
                        int r2 = r1 - (cum + excl);
                        float pv = (lane < l) ? s : 0.0f;
                        #pragma unroll
                        for (int off = 16; off; off >>= 1)
                            pv += __shfl_xor_sync(0xFFFFFFFFu, pv, off);
                        int   cl = __shfl_sync(0xFFFFFFFFu, c, l);
                        float sl = __shfl_sync(0xFFFFFFFFu, s, l);
                        float lo = __uint_as_float((unsigned)(BLO + j0 + l) << 19);
                        float mbar = sl / (float)cl;
                        float partial = (float)r2 * lo
                                      + (mbar - lo) * ((float)r2 * (float)r2) / (float)cl;
                        loss = below + acc + pv + partial;
                        done = 1;
                        break;
                    }
                    cum += total;
                    float cssum = s;
                    #pragma unroll
                    for (int off = 16; off; off >>= 1)
                        cssum += __shfl_xor_sync(0xFFFFFFFFu, cssum, off);
                    acc += cssum;
                }
                if (!done) loss = below + acc;     // defensive (bracket miss high)
            }
        }
        if (lane == 0) { d_loss[b] = loss; d_div[b] = div; }
    }
}

// ---- final reduce: 1 warp ----
__global__ void k_reduce(float* __restrict__ out) {
    int lane = threadIdx.x;
    float L = d_loss[lane];
    float D = d_div[lane];
    #pragma unroll
    for (int off = 16; off; off >>= 1) {
        L += __shfl_xor_sync(0xFFFFFFFFu, L, off);
        D += __shfl_xor_sync(0xFFFFFFFFu, D, off);
    }
    if (lane == 0)
        out[0] = (D == 0.0f) ? 0.0f : L / fmaxf(D, 1e-30f);
}

extern "C" void kernel_launch(void* const* d_in, const int* in_sizes, int n_in,
                              void* d_out, int out_size) {
    const float4* p = (const float4*)d_in[0];   // prediction f32 [32,512,512]
    const float4* t = (const float4*)d_in[1];   // target     f32 [32,512,512]
    const int4*   m = (const int4*)d_in[2];     // mask       i32 [32,512,512]
    float* out = (float*)d_out;

    k_sample<<<NBATCH, 256>>>(p, t, m);
    k_passB<<<NBATCH * BPB, 256>>>(p, t, m);
    k_final<<<NBATCH, 256>>>();
    k_reduce<<<1, 32>>>(out);
}